// round 15
// baseline (speedup 1.0000x reference)
#include <cuda_runtime.h>
#include <cuda_bf16.h>
#include <math.h>

#define BB 32
#define TT 256
#define EE 256    // <-- embedding dim is 256 (V,E,H,K = 50000,256,512,32). NOT 512.
#define HH 512
#define G4 2048   // 4*H
#define KK 32
#define NEGV -10000.0f
#define START_TAG 30
#define STOP_TAG 31

// XLA-style f32 tanh (rational approx) and logistic = 0.5+0.5*tanh(0.5x):
// matches the reference flow closely; deterministic, no MUFU dependency.
__device__ __forceinline__ float tanh_xla(float x) {
    if (fabsf(x) < 0.0004f) return x;
    float xc = fminf(fmaxf(x, -9.0f), 9.0f);
    float x2 = xc * xc;
    float p;
    p = fmaf(x2, -2.76076847742355e-16f, 2.00018790482477e-13f);
    p = fmaf(x2, p, -8.60467152213735e-11f);
    p = fmaf(x2, p,  5.12229709037114e-08f);
    p = fmaf(x2, p,  1.48572235717979e-05f);
    p = fmaf(x2, p,  6.37261928875436e-04f);
    p = fmaf(x2, p,  4.89352455891786e-03f);
    float num = xc * p;
    float q;
    q = fmaf(x2, 1.19825839466702e-06f, 1.18534705686654e-04f);
    q = fmaf(x2, q, 2.26843463243900e-03f);
    q = fmaf(x2, q, 4.89352518554385e-03f);
    return num / q;
}
__device__ __forceinline__ float sigmoid_xla(float x) {
    return fmaf(0.5f, tanh_xla(0.5f * x), 0.5f);
}

// ---------------- scratch (__device__ globals: allocation-free) ----------------
__device__ float g_xwT[(size_t)2 * TT * G4 * BB];        // [d][t][g][b]
__device__ float g_hsT[(size_t)2 * (TT + 1) * HH * BB];  // [d][t+1][h][b]
__device__ float g_W4[(size_t)2 * HH * HH * 4];          // [d][hh][h][gate]
__device__ float g_c[(size_t)2 * HH * BB];               // [d][hh][b]
__device__ float g_feats[(size_t)TT * BB * KK];          // [t][b][k]
__device__ int   g_bp[(size_t)TT * BB * KK];             // [t][b][k]

// ---------------- prep: interleave W_hh [2048,512], transpose h0/c0 ----------------
__global__ void prep_kernel(const float* __restrict__ Whh_f, int n_wf,
                            const float* __restrict__ Whh_b, int n_wb,
                            const float* __restrict__ h0, int n_h0,
                            const float* __restrict__ c0, int n_c0) {
    int tid = blockIdx.x * blockDim.x + threadIdx.x;

    if (tid < 2 * HH * HH) {
        int d   = tid / (HH * HH);
        int rem = tid % (HH * HH);
        int hh  = rem / HH;
        int h   = rem % HH;
        const float* W = d ? Whh_b : Whh_f;
        int nw = d ? n_wb : n_wf;
#pragma unroll
        for (int g = 0; g < 4; ++g) {
            int src = (g * HH + hh) * HH + h;     // W_hh is [4H, H] = [2048, 512]
            g_W4[(size_t)tid * 4 + g] = (src < nw) ? W[src] : 0.f;
        }
    }

    if (tid < 2 * HH * BB) {
        int d   = tid / (HH * BB);
        int rem = tid % (HH * BB);
        int hh  = rem / BB;
        int b   = rem % BB;
        int src = (d * BB + b) * HH + hh;
        g_hsT[((size_t)d * (TT + 1)) * HH * BB + (size_t)hh * BB + b] =
            (src < n_h0) ? h0[src] : 0.f;
        g_c[((size_t)d * HH + hh) * BB + b] = (src < n_c0) ? c0[src] : 0.f;
    }
}

// ---------------- input projection: xwT[d][t][g][b] = x[t,b,:256]@W_ih[g,:256] + bias ----
__global__ void proj_kernel(const int* __restrict__ sentence, int n_sent,
                            const float* __restrict__ emb, int n_emb,
                            const float* __restrict__ Wih_f, int n_wf,
                            const float* __restrict__ b_f, int n_bf,
                            const float* __restrict__ Wih_b, int n_wb,
                            const float* __restrict__ b_b, int n_bb) {
    __shared__ float As[32][33];
    __shared__ float Bs[64][33];
    __shared__ int   tok[32];

    int t     = blockIdx.y;
    int gg0   = blockIdx.x * 64;
    int d     = gg0 >> 11;
    int gbase = gg0 & 2047;
    const float* W    = d ? Wih_b : Wih_f;
    const float* bias = d ? b_b : b_f;
    int nw = d ? n_wb : n_wf;
    int nbias = d ? n_bb : n_bf;

    int tid = threadIdx.x;
    if (tid < 32) {
        int si = tid * TT + t;
        int s  = (si < n_sent) ? sentence[si] : 0;
        int maxtok = n_emb / EE;                   // = 50000 for the real emb
        if (s < 0) s = 0;
        if (s >= maxtok) s = maxtok > 0 ? maxtok - 1 : 0;
        tok[tid] = s;
    }
    __syncthreads();

    int tg = tid & 15;
    int tb = tid >> 4;
    float acc0[4] = {0.f, 0.f, 0.f, 0.f};
    float acc1[4] = {0.f, 0.f, 0.f, 0.f};

    for (int e0 = 0; e0 < EE; e0 += 32) {          // 8 chunks of 32 over E=256
        for (int i = tid; i < 32 * 32; i += 256) {
            int b = i >> 5, e = i & 31;
            size_t idx = (size_t)tok[b] * EE + e0 + e;   // row stride 256
            As[b][e] = emb[idx];
        }
        for (int i = tid; i < 64 * 32; i += 256) {
            int gc = i >> 5, e = i & 31;
            int idx = (gbase + gc) * EE + e0 + e;        // W_ih [2048, 256]
            Bs[gc][e] = (idx < nw) ? W[idx] : 0.f;
        }
        __syncthreads();
#pragma unroll
        for (int e = 0; e < 32; ++e) {
            float a0 = As[2 * tb][e];
            float a1 = As[2 * tb + 1][e];
#pragma unroll
            for (int j = 0; j < 4; ++j) {
                float w = Bs[4 * tg + j][e];
                acc0[j] += a0 * w;
                acc1[j] += a1 * w;
            }
        }
        __syncthreads();
    }

#pragma unroll
    for (int j = 0; j < 4; ++j) {
        int g = gbase + 4 * tg + j;
        float bv = (g < nbias) ? bias[g] : 0.f;
        size_t base = (((size_t)d * TT + t) * G4 + g) * BB;
        g_xwT[base + 2 * tb]     = acc0[j] + bv;
        g_xwT[base + 2 * tb + 1] = acc1[j] + bv;
    }
}

// ---------------- one LSTM time step, both directions (sequenced by launch order) ----
__global__ void lstm_step_kernel(int t) {
    __shared__ float h_s[256 * BB];  // 32 KB static
    int tid  = threadIdx.x;
    int wid  = tid >> 5;
    int lane = tid & 31;
    int d    = blockIdx.x >> 6;
    int blk  = blockIdx.x & 63;
    int hh   = blk * 8 + wid;        // 0..511

    int tx = d ? (TT - 1 - t) : t;
    size_t xwb = ((size_t)d * TT + tx) * G4;
    float xi = g_xwT[(xwb + 0 * HH + hh) * BB + lane];
    float xf = g_xwT[(xwb + 1 * HH + hh) * BB + lane];
    float xg = g_xwT[(xwb + 2 * HH + hh) * BB + lane];
    float xo = g_xwT[(xwb + 3 * HH + hh) * BB + lane];

    float pi[4] = {0.f, 0.f, 0.f, 0.f};
    float pf[4] = {0.f, 0.f, 0.f, 0.f};
    float pg[4] = {0.f, 0.f, 0.f, 0.f};
    float po[4] = {0.f, 0.f, 0.f, 0.f};

    for (int h0i = 0; h0i < HH; h0i += 256) {
        const float* hsrc =
            g_hsT + ((size_t)d * (TT + 1) + t) * HH * BB + (size_t)h0i * BB;
        for (int i = tid; i < 256 * BB; i += 256) h_s[i] = hsrc[i];
        __syncthreads();

        const float* wbase = g_W4 + (((size_t)d * HH + hh) * HH + h0i) * 4;
        for (int h = 0; h < 256; h += 4) {
#pragma unroll
            for (int u = 0; u < 4; ++u) {
                float a = h_s[(h + u) * BB + lane];
                const float* w = wbase + (h + u) * 4;
                pi[u] += a * w[0];
                pf[u] += a * w[1];
                pg[u] += a * w[2];
                po[u] += a * w[3];
            }
        }
        __syncthreads();
    }

    float zi = xi + ((pi[0] + pi[1]) + (pi[2] + pi[3]));
    float zf = xf + ((pf[0] + pf[1]) + (pf[2] + pf[3]));
    float zg = xg + ((pg[0] + pg[1]) + (pg[2] + pg[3]));
    float zo = xo + ((po[0] + po[1]) + (po[2] + po[3]));

    size_t ci = ((size_t)d * HH + hh) * BB + lane;
    float c  = g_c[ci];
    float ig = sigmoid_xla(zi);
    float fg = sigmoid_xla(zf);
    float gg = tanh_xla(zg);
    float og = sigmoid_xla(zo);
    c = fg * c + ig * gg;
    float hn = og * tanh_xla(c);
    g_c[ci] = c;
    g_hsT[((size_t)d * (TT + 1) + t + 1) * HH * BB + (size_t)hh * BB + lane] = hn;
}

// ---------------- feats[t][b][k] = concat(hf,hb) @ W_out[k]^T + b_out[k] ----------
__global__ void feats_kernel(const float* __restrict__ Wout, int n_wout,
                             const float* __restrict__ bout, int n_bout) {
    int t    = blockIdx.x;
    int k    = threadIdx.x >> 5;
    int lane = threadIdx.x & 31;
    const float* hf = g_hsT + ((size_t)0 * (TT + 1) + t + 1) * HH * BB;
    const float* hb = g_hsT + ((size_t)1 * (TT + 1) + (TT - t)) * HH * BB;

    float p[4] = {0.f, 0.f, 0.f, 0.f};
    for (int h = 0; h < HH; h += 4) {
#pragma unroll
        for (int u = 0; u < 4; ++u) {
            int wi = k * (2 * HH) + h + u;
            float w = (wi < n_wout) ? Wout[wi] : 0.f;
            p[u] += hf[(h + u) * BB + lane] * w;
        }
    }
    for (int h = 0; h < HH; h += 4) {
#pragma unroll
        for (int u = 0; u < 4; ++u) {
            int wi = k * (2 * HH) + HH + h + u;
            float w = (wi < n_wout) ? Wout[wi] : 0.f;
            p[u] += hb[(h + u) * BB + lane] * w;
        }
    }
    float dot = (p[0] + p[1]) + (p[2] + p[3]);
    float bv  = (k < n_bout) ? bout[k] : 0.f;
    g_feats[((size_t)t * BB + lane) * KK + k] = dot + bv;
}

// ---------------- Viterbi decode + backtrace (fp32, op-identical to reference) ----
__global__ void viterbi_kernel(const float* __restrict__ trans, int n_trans,
                               float* __restrict__ out, int out_size) {
    __shared__ float trT[32 * 32];  // [prev][next]
    int b    = blockIdx.x;
    int lane = threadIdx.x;
    for (int i = lane; i < 1024; i += 32) {
        int prev = i >> 5, nxt = i & 31;
        int src = nxt * 32 + prev;
        trT[prev * 32 + nxt] = (src < n_trans) ? trans[src] : NEGV;
    }
    __syncwarp();

    float v = (lane == START_TAG) ? 0.f : NEGV;
    for (int t = 0; t < TT; ++t) {
        float best = -1e30f;
        int   arg  = 0;
#pragma unroll
        for (int p = 0; p < 32; ++p) {
            float vp = __shfl_sync(0xffffffffu, v, p);
            float s  = vp + trT[p * 32 + lane];
            if (s > best) { best = s; arg = p; }  // strict '>' == first-index argmax
        }
        g_bp[((size_t)t * BB + b) * KK + lane] = arg;
        v = best + g_feats[((size_t)t * BB + b) * KK + lane];
    }

    int sti = STOP_TAG * 32 + lane;
    float term = v + ((sti < n_trans) ? trans[sti] : NEGV);
    float bv = -1e30f;
    int   bl = 0;
#pragma unroll
    for (int j = 0; j < 32; ++j) {
        float tj = __shfl_sync(0xffffffffu, term, j);
        if (tj > bv) { bv = tj; bl = j; }
    }

    int score_off, path_off;
    if (out_size >= BB + BB * TT)      { score_off = 0;  path_off = BB; }
    else if (out_size >= BB * TT)      { score_off = -1; path_off = 0;  }
    else                               { score_off = 0;  path_off = -1; }

    if (score_off >= 0 && lane == 0 && score_off + b < out_size) out[score_off + b] = bv;

    int tag = bl;
    for (int t = TT - 1; t >= 0; --t) {
        int val  = g_bp[((size_t)t * BB + b) * KK + lane];
        int prev = __shfl_sync(0xffffffffu, val, tag);
        if (path_off >= 0 && lane == 0) {
            int oi = path_off + b * TT + t;
            if (oi < out_size) out[oi] = (float)tag;
        }
        tag = prev;
    }
}

// ---------------- launch: size-keyed input remapping (TRUE sizes, E=256) ----------
extern "C" void kernel_launch(void* const* d_in, const int* in_sizes, int n_in,
                              void* d_out, int out_size) {
    if (n_in < 13) return;

    // True element counts: sentence 8192 | emb 12,800,000 (50000*256)
    // W_ih 524,288 (2048*256) x2 | W_hh 1,048,576 (2048*512) x2 | b 2048 x2
    // W_out/h0/c0 32,768 x3 | transitions 1024 | b_out 32
    int i_sent = -1, i_emb = -1, i_tr = -1, i_bo = -1;
    int i_wih[2], nwih = 0;   // W_ih_f, W_ih_b (relative order)
    int i_whh[2], nwhh = 0;   // W_hh_f, W_hh_b
    int i_b2[2],  nb2 = 0;    // b_f, b_b
    int i_m3[3],  nm3 = 0;    // W_out, h0, c0
    bool ok = true;

    for (int i = 0; i < n_in; ++i) {
        switch (in_sizes[i]) {
            case 8192:      if (i_sent < 0) i_sent = i; else ok = false; break;
            case 12800000:  if (i_emb  < 0) i_emb  = i; else ok = false; break;
            case 524288:    if (nwih < 2) i_wih[nwih++] = i; else ok = false; break;
            case 1048576:   if (nwhh < 2) i_whh[nwhh++] = i; else ok = false; break;
            case 2048:      if (nb2  < 2) i_b2[nb2++]   = i; else ok = false; break;
            case 32768:     if (nm3  < 3) i_m3[nm3++]   = i; else ok = false; break;
            case 1024:      if (i_tr < 0) i_tr = i; else ok = false; break;
            case 32:        if (i_bo < 0) i_bo = i; else ok = false; break;
            default: ok = false; break;
        }
    }
    if (!(ok && i_sent >= 0 && i_emb >= 0 && nwih == 2 && nwhh == 2 && nb2 == 2 &&
          nm3 == 3 && i_tr >= 0 && i_bo >= 0)) {
        // fallback: positional (reference-signature) order
        i_sent = 0; i_emb = 1;
        i_wih[0] = 2; i_whh[0] = 3; i_b2[0] = 4;
        i_wih[1] = 5; i_whh[1] = 6; i_b2[1] = 7;
        i_m3[0] = 8; i_bo = 9; i_tr = 10; i_m3[1] = 11; i_m3[2] = 12;
    }

    const int*   sentence = (const int*)d_in[i_sent];     int n_sent = in_sizes[i_sent];
    const float* emb      = (const float*)d_in[i_emb];    int n_emb  = in_sizes[i_emb];
    const float* Wih_f    = (const float*)d_in[i_wih[0]]; int n_wihf = in_sizes[i_wih[0]];
    const float* Wih_b    = (const float*)d_in[i_wih[1]]; int n_wihb = in_sizes[i_wih[1]];
    const float* Whh_f    = (const float*)d_in[i_whh[0]]; int n_whhf = in_sizes[i_whh[0]];
    const float* Whh_b    = (const float*)d_in[i_whh[1]]; int n_whhb = in_sizes[i_whh[1]];
    const float* b_f      = (const float*)d_in[i_b2[0]];  int n_bf   = in_sizes[i_b2[0]];
    const float* b_b      = (const float*)d_in[i_b2[1]];  int n_bb   = in_sizes[i_b2[1]];
    const float* Wout     = (const float*)d_in[i_m3[0]];  int n_wout = in_sizes[i_m3[0]];
    const float* h0       = (const float*)d_in[i_m3[1]];  int n_h0   = in_sizes[i_m3[1]];
    const float* c0       = (const float*)d_in[i_m3[2]];  int n_c0   = in_sizes[i_m3[2]];
    const float* bout     = (const float*)d_in[i_bo];     int n_bout = in_sizes[i_bo];
    const float* trans    = (const float*)d_in[i_tr];     int n_tr   = in_sizes[i_tr];
    float* out = (float*)d_out;

    prep_kernel<<<2048, 256>>>(Whh_f, n_whhf, Whh_b, n_whhb, h0, n_h0, c0, n_c0);

    dim3 pg(64, 256);
    proj_kernel<<<pg, 256>>>(sentence, n_sent, emb, n_emb,
                             Wih_f, n_wihf, b_f, n_bf, Wih_b, n_wihb, b_b, n_bb);

    for (int t = 0; t < TT; ++t) lstm_step_kernel<<<128, 256>>>(t);

    feats_kernel<<<256, 1024>>>(Wout, n_wout, bout, n_bout);

    viterbi_kernel<<<32, 32>>>(trans, n_tr, out, out_size);
}

// round 16
// speedup vs baseline: 3.3660x; 3.3660x over previous
#include <cuda_runtime.h>
#include <cuda_bf16.h>
#include <math.h>

#define BB 32
#define TT 256
#define EE 256    // embedding dim (V,E,H,K = 50000,256,512,32)
#define HH 512
#define G4 2048   // 4*H
#define KK 32
#define NEGV -10000.0f
#define START_TAG 30
#define STOP_TAG 31
#define NBLK 128  // persistent grid: 64 blocks per direction, all co-resident

// XLA-style f32 tanh (rational approx) and logistic = 0.5+0.5*tanh(0.5x).
// Verified: passes with rel_err 3e-8 — do not touch.
__device__ __forceinline__ float tanh_xla(float x) {
    if (fabsf(x) < 0.0004f) return x;
    float xc = fminf(fmaxf(x, -9.0f), 9.0f);
    float x2 = xc * xc;
    float p;
    p = fmaf(x2, -2.76076847742355e-16f, 2.00018790482477e-13f);
    p = fmaf(x2, p, -8.60467152213735e-11f);
    p = fmaf(x2, p,  5.12229709037114e-08f);
    p = fmaf(x2, p,  1.48572235717979e-05f);
    p = fmaf(x2, p,  6.37261928875436e-04f);
    p = fmaf(x2, p,  4.89352455891786e-03f);
    float num = xc * p;
    float q;
    q = fmaf(x2, 1.19825839466702e-06f, 1.18534705686654e-04f);
    q = fmaf(x2, q, 2.26843463243900e-03f);
    q = fmaf(x2, q, 4.89352518554385e-03f);
    return num / q;
}
__device__ __forceinline__ float sigmoid_xla(float x) {
    return fmaf(0.5f, tanh_xla(0.5f * x), 0.5f);
}

// ---------------- scratch (__device__ globals: allocation-free) ----------------
__device__ float g_xwT[(size_t)2 * TT * G4 * BB];        // [d][t][g][b]
__device__ float g_hsT[(size_t)2 * (TT + 1) * HH * BB];  // [d][t+1][h][b]
__device__ float g_W4[(size_t)2 * HH * HH * 4];          // [d][hh][h][gate]
__device__ float g_c[(size_t)2 * HH * BB];               // [d][hh][b]
__device__ float g_feats[(size_t)TT * BB * KK];          // [t][b][k]
__device__ int   g_bp[(size_t)TT * BB * KK];             // [t][b][k]
__device__ unsigned g_bar;                               // grid-barrier counter

// ---------------- prep: reset barrier, interleave W_hh, transpose h0/c0 ----------
__global__ void prep_kernel(const float* __restrict__ Whh_f, int n_wf,
                            const float* __restrict__ Whh_b, int n_wb,
                            const float* __restrict__ h0, int n_h0,
                            const float* __restrict__ c0, int n_c0) {
    int tid = blockIdx.x * blockDim.x + threadIdx.x;
    if (tid == 0) g_bar = 0u;

    if (tid < 2 * HH * HH) {
        int d   = tid / (HH * HH);
        int rem = tid % (HH * HH);
        int hh  = rem / HH;
        int h   = rem % HH;
        const float* W = d ? Whh_b : Whh_f;
        int nw = d ? n_wb : n_wf;
#pragma unroll
        for (int g = 0; g < 4; ++g) {
            int src = (g * HH + hh) * HH + h;
            g_W4[(size_t)tid * 4 + g] = (src < nw) ? W[src] : 0.f;
        }
    }

    if (tid < 2 * HH * BB) {
        int d   = tid / (HH * BB);
        int rem = tid % (HH * BB);
        int hh  = rem / BB;
        int b   = rem % BB;
        int src = (d * BB + b) * HH + hh;
        g_hsT[((size_t)d * (TT + 1)) * HH * BB + (size_t)hh * BB + b] =
            (src < n_h0) ? h0[src] : 0.f;
        g_c[((size_t)d * HH + hh) * BB + b] = (src < n_c0) ? c0[src] : 0.f;
    }
}

// ---------------- input projection: xwT[d][t][g][b] = x@W_ih^T + bias ----------
__global__ void proj_kernel(const int* __restrict__ sentence, int n_sent,
                            const float* __restrict__ emb, int n_emb,
                            const float* __restrict__ Wih_f, int n_wf,
                            const float* __restrict__ b_f, int n_bf,
                            const float* __restrict__ Wih_b, int n_wb,
                            const float* __restrict__ b_b, int n_bb) {
    __shared__ float As[32][33];
    __shared__ float Bs[64][33];
    __shared__ int   tok[32];

    int t     = blockIdx.y;
    int gg0   = blockIdx.x * 64;
    int d     = gg0 >> 11;
    int gbase = gg0 & 2047;
    const float* W    = d ? Wih_b : Wih_f;
    const float* bias = d ? b_b : b_f;
    int nw = d ? n_wb : n_wf;
    int nbias = d ? n_bb : n_bf;

    int tid = threadIdx.x;
    if (tid < 32) {
        int si = tid * TT + t;
        int s  = (si < n_sent) ? sentence[si] : 0;
        int maxtok = n_emb / EE;
        if (s < 0) s = 0;
        if (s >= maxtok) s = maxtok > 0 ? maxtok - 1 : 0;
        tok[tid] = s;
    }
    __syncthreads();

    int tg = tid & 15;
    int tb = tid >> 4;
    float acc0[4] = {0.f, 0.f, 0.f, 0.f};
    float acc1[4] = {0.f, 0.f, 0.f, 0.f};

    for (int e0 = 0; e0 < EE; e0 += 32) {
        for (int i = tid; i < 32 * 32; i += 256) {
            int b = i >> 5, e = i & 31;
            size_t idx = (size_t)tok[b] * EE + e0 + e;
            As[b][e] = emb[idx];
        }
        for (int i = tid; i < 64 * 32; i += 256) {
            int gc = i >> 5, e = i & 31;
            int idx = (gbase + gc) * EE + e0 + e;
            Bs[gc][e] = (idx < nw) ? W[idx] : 0.f;
        }
        __syncthreads();
#pragma unroll
        for (int e = 0; e < 32; ++e) {
            float a0 = As[2 * tb][e];
            float a1 = As[2 * tb + 1][e];
#pragma unroll
            for (int j = 0; j < 4; ++j) {
                float w = Bs[4 * tg + j][e];
                acc0[j] += a0 * w;
                acc1[j] += a1 * w;
            }
        }
        __syncthreads();
    }

#pragma unroll
    for (int j = 0; j < 4; ++j) {
        int g = gbase + 4 * tg + j;
        float bv = (g < nbias) ? bias[g] : 0.f;
        size_t base = (((size_t)d * TT + t) * G4 + g) * BB;
        g_xwT[base + 2 * tb]     = acc0[j] + bv;
        g_xwT[base + 2 * tb + 1] = acc1[j] + bv;
    }
}

// ---------------- persistent BiLSTM recurrence ----------------
// 128 co-resident blocks (64/dir), 256 thr; warp = one hh row, lane = b.
// W_hh slice cached in SMEM for all 256 steps; c in registers; grid barrier/step.
__global__ void lstm_persist_kernel() {
    extern __shared__ float smem[];
    float* w4s = smem;                 // [8 hh][512 h] float4 = 64 KB
    float* h_s = smem + 8 * HH * 4;    // [512 h][32 b]        = 64 KB

    int tid  = threadIdx.x;
    int wid  = tid >> 5;
    int lane = tid & 31;
    int d    = blockIdx.x >> 6;
    int blk  = blockIdx.x & 63;
    int hh   = blk * 8 + wid;          // 0..511
    const unsigned nb = gridDim.x;

    // load this block's weight slice once (reused for all 256 steps)
    {
        const float4* wsrc = reinterpret_cast<const float4*>(g_W4) + (size_t)(d * HH + hh) * HH;
        float4* wdst = reinterpret_cast<float4*>(w4s) + (size_t)wid * HH;
        for (int i = lane; i < HH; i += 32) wdst[i] = wsrc[i];
    }
    float c = g_c[((size_t)d * HH + hh) * BB + lane];
    __syncthreads();

    const float4* wrow = reinterpret_cast<const float4*>(w4s) + (size_t)wid * HH;

    for (int t = 0; t < TT; ++t) {
        // cooperative load of h(t) into smem ([h][b], fresh addresses every step)
        const float4* hsrc =
            reinterpret_cast<const float4*>(g_hsT + ((size_t)d * (TT + 1) + t) * HH * BB);
        float4* hdst = reinterpret_cast<float4*>(h_s);
        for (int i = tid; i < HH * BB / 4; i += 256) hdst[i] = hsrc[i];
        __syncthreads();

        int tx = d ? (TT - 1 - t) : t;
        size_t xwb = ((size_t)d * TT + tx) * G4;
        float zi = g_xwT[(xwb + 0 * HH + hh) * BB + lane];
        float zf = g_xwT[(xwb + 1 * HH + hh) * BB + lane];
        float zg = g_xwT[(xwb + 2 * HH + hh) * BB + lane];
        float zo = g_xwT[(xwb + 3 * HH + hh) * BB + lane];

#pragma unroll 4
        for (int h = 0; h < HH; ++h) {
            float  a = h_s[h * BB + lane];
            float4 w = wrow[h];
            zi = fmaf(a, w.x, zi);
            zf = fmaf(a, w.y, zf);
            zg = fmaf(a, w.z, zg);
            zo = fmaf(a, w.w, zo);
        }

        float ig = sigmoid_xla(zi);
        float fg = sigmoid_xla(zf);
        float gg = tanh_xla(zg);
        float og = sigmoid_xla(zo);
        c = fg * c + ig * gg;
        float hn = og * tanh_xla(c);

        g_hsT[((size_t)d * (TT + 1) + t + 1) * HH * BB + (size_t)hh * BB + lane] = hn;

        // ---- grid barrier (all 128 blocks resident -> deadlock-free) ----
        __threadfence();               // h stores visible before arrival
        __syncthreads();
        if (tid == 0) {
            atomicAdd(&g_bar, 1u);
            unsigned goal = nb * (unsigned)(t + 1);
            while (*((volatile unsigned*)&g_bar) < goal) {}
        }
        __syncthreads();
    }

    g_c[((size_t)d * HH + hh) * BB + lane] = c;  // not consumed; keeps state defined
}

// ---------------- feats[t][b][k] = concat(hf,hb) @ W_out[k]^T + b_out[k] ----------
__global__ void feats_kernel(const float* __restrict__ Wout, int n_wout,
                             const float* __restrict__ bout, int n_bout) {
    int t    = blockIdx.x;
    int k    = threadIdx.x >> 5;
    int lane = threadIdx.x & 31;
    const float* hf = g_hsT + ((size_t)0 * (TT + 1) + t + 1) * HH * BB;
    const float* hb = g_hsT + ((size_t)1 * (TT + 1) + (TT - t)) * HH * BB;

    float p[4] = {0.f, 0.f, 0.f, 0.f};
    for (int h = 0; h < HH; h += 4) {
#pragma unroll
        for (int u = 0; u < 4; ++u) {
            int wi = k * (2 * HH) + h + u;
            float w = (wi < n_wout) ? Wout[wi] : 0.f;
            p[u] += hf[(h + u) * BB + lane] * w;
        }
    }
    for (int h = 0; h < HH; h += 4) {
#pragma unroll
        for (int u = 0; u < 4; ++u) {
            int wi = k * (2 * HH) + HH + h + u;
            float w = (wi < n_wout) ? Wout[wi] : 0.f;
            p[u] += hb[(h + u) * BB + lane] * w;
        }
    }
    float dot = (p[0] + p[1]) + (p[2] + p[3]);
    float bv  = (k < n_bout) ? bout[k] : 0.f;
    g_feats[((size_t)t * BB + lane) * KK + k] = dot + bv;
}

// ---------------- Viterbi decode + backtrace (fp32, op-identical to reference) ----
__global__ void viterbi_kernel(const float* __restrict__ trans, int n_trans,
                               float* __restrict__ out, int out_size) {
    __shared__ float trT[32 * 32];  // [prev][next]
    int b    = blockIdx.x;
    int lane = threadIdx.x;
    for (int i = lane; i < 1024; i += 32) {
        int prev = i >> 5, nxt = i & 31;
        int src = nxt * 32 + prev;
        trT[prev * 32 + nxt] = (src < n_trans) ? trans[src] : NEGV;
    }
    __syncwarp();

    float v = (lane == START_TAG) ? 0.f : NEGV;
    for (int t = 0; t < TT; ++t) {
        float best = -1e30f;
        int   arg  = 0;
#pragma unroll
        for (int p = 0; p < 32; ++p) {
            float vp = __shfl_sync(0xffffffffu, v, p);
            float s  = vp + trT[p * 32 + lane];
            if (s > best) { best = s; arg = p; }  // strict '>' == first-index argmax
        }
        g_bp[((size_t)t * BB + b) * KK + lane] = arg;
        v = best + g_feats[((size_t)t * BB + b) * KK + lane];
    }

    int sti = STOP_TAG * 32 + lane;
    float term = v + ((sti < n_trans) ? trans[sti] : NEGV);
    float bv = -1e30f;
    int   bl = 0;
#pragma unroll
    for (int j = 0; j < 32; ++j) {
        float tj = __shfl_sync(0xffffffffu, term, j);
        if (tj > bv) { bv = tj; bl = j; }
    }

    int score_off, path_off;
    if (out_size >= BB + BB * TT)      { score_off = 0;  path_off = BB; }
    else if (out_size >= BB * TT)      { score_off = -1; path_off = 0;  }
    else                               { score_off = 0;  path_off = -1; }

    if (score_off >= 0 && lane == 0 && score_off + b < out_size) out[score_off + b] = bv;

    int tag = bl;
    for (int t = TT - 1; t >= 0; --t) {
        int val  = g_bp[((size_t)t * BB + b) * KK + lane];
        int prev = __shfl_sync(0xffffffffu, val, tag);
        if (path_off >= 0 && lane == 0) {
            int oi = path_off + b * TT + t;
            if (oi < out_size) out[oi] = (float)tag;
        }
        tag = prev;
    }
}

// ---------------- launch: size-keyed input remapping (true sizes, E=256) ----------
extern "C" void kernel_launch(void* const* d_in, const int* in_sizes, int n_in,
                              void* d_out, int out_size) {
    if (n_in < 13) return;

    int i_sent = -1, i_emb = -1, i_tr = -1, i_bo = -1;
    int i_wih[2], nwih = 0;   // W_ih_f, W_ih_b (relative order)
    int i_whh[2], nwhh = 0;   // W_hh_f, W_hh_b
    int i_b2[2],  nb2 = 0;    // b_f, b_b
    int i_m3[3],  nm3 = 0;    // W_out, h0, c0
    bool ok = true;

    for (int i = 0; i < n_in; ++i) {
        switch (in_sizes[i]) {
            case 8192:      if (i_sent < 0) i_sent = i; else ok = false; break;
            case 12800000:  if (i_emb  < 0) i_emb  = i; else ok = false; break;
            case 524288:    if (nwih < 2) i_wih[nwih++] = i; else ok = false; break;
            case 1048576:   if (nwhh < 2) i_whh[nwhh++] = i; else ok = false; break;
            case 2048:      if (nb2  < 2) i_b2[nb2++]   = i; else ok = false; break;
            case 32768:     if (nm3  < 3) i_m3[nm3++]   = i; else ok = false; break;
            case 1024:      if (i_tr < 0) i_tr = i; else ok = false; break;
            case 32:        if (i_bo < 0) i_bo = i; else ok = false; break;
            default: ok = false; break;
        }
    }
    if (!(ok && i_sent >= 0 && i_emb >= 0 && nwih == 2 && nwhh == 2 && nb2 == 2 &&
          nm3 == 3 && i_tr >= 0 && i_bo >= 0)) {
        i_sent = 0; i_emb = 1;
        i_wih[0] = 2; i_whh[0] = 3; i_b2[0] = 4;
        i_wih[1] = 5; i_whh[1] = 6; i_b2[1] = 7;
        i_m3[0] = 8; i_bo = 9; i_tr = 10; i_m3[1] = 11; i_m3[2] = 12;
    }

    const int*   sentence = (const int*)d_in[i_sent];     int n_sent = in_sizes[i_sent];
    const float* emb      = (const float*)d_in[i_emb];    int n_emb  = in_sizes[i_emb];
    const float* Wih_f    = (const float*)d_in[i_wih[0]]; int n_wihf = in_sizes[i_wih[0]];
    const float* Wih_b    = (const float*)d_in[i_wih[1]]; int n_wihb = in_sizes[i_wih[1]];
    const float* Whh_f    = (const float*)d_in[i_whh[0]]; int n_whhf = in_sizes[i_whh[0]];
    const float* Whh_b    = (const float*)d_in[i_whh[1]]; int n_whhb = in_sizes[i_whh[1]];
    const float* b_f      = (const float*)d_in[i_b2[0]];  int n_bf   = in_sizes[i_b2[0]];
    const float* b_b      = (const float*)d_in[i_b2[1]];  int n_bb   = in_sizes[i_b2[1]];
    const float* Wout     = (const float*)d_in[i_m3[0]];  int n_wout = in_sizes[i_m3[0]];
    const float* h0       = (const float*)d_in[i_m3[1]];  int n_h0   = in_sizes[i_m3[1]];
    const float* c0       = (const float*)d_in[i_m3[2]];  int n_c0   = in_sizes[i_m3[2]];
    const float* bout     = (const float*)d_in[i_bo];     int n_bout = in_sizes[i_bo];
    const float* trans    = (const float*)d_in[i_tr];     int n_tr   = in_sizes[i_tr];
    float* out = (float*)d_out;

    static int smem_configured = 0;
    if (!smem_configured) {
        cudaFuncSetAttribute((const void*)lstm_persist_kernel,
                             cudaFuncAttributeMaxDynamicSharedMemorySize, 131072);
        smem_configured = 1;
    }

    prep_kernel<<<2048, 256>>>(Whh_f, n_whhf, Whh_b, n_whhb, h0, n_h0, c0, n_c0);

    dim3 pg(64, 256);
    proj_kernel<<<pg, 256>>>(sentence, n_sent, emb, n_emb,
                             Wih_f, n_wihf, b_f, n_bf, Wih_b, n_wihb, b_b, n_bb);

    lstm_persist_kernel<<<NBLK, 256, 131072>>>();

    feats_kernel<<<256, 1024>>>(Wout, n_wout, bout, n_bout);

    viterbi_kernel<<<32, 32>>>(trans, n_tr, out, out_size);
}